// round 1
// baseline (speedup 1.0000x reference)
#include <cuda_runtime.h>
#include <math.h>

#define V 30522
#define NBATCH 2
#define SLEN 512
#define DIM 768
#define NJ 12
#define NBK 4
#define NUM_LABELS 7
#define M_TOK (NBATCH*SLEN)   /* 1024 */
#define KDIM (13*DIM)         /* 9984 */
#define GDIM (NJ*DIM)         /* 9216 */

#define BM 64
#define BN 64
#define BK 16

// ---------------- scratch (device globals; no allocation allowed) ----------------
__device__ float g_table[(size_t)V*DIM];          // vocab dict rows
__device__ int   g_present[V];
__device__ int   g_lastpos[V];
__device__ float g_rij[(size_t)M_TOK*KDIM];       // [seq | n_flat] per token
__device__ float g_c[(size_t)M_TOK*GDIM];         // gated neighbors (active chunks only)
__device__ float g_combined[(size_t)M_TOK*2*DIM]; // [mix | seq]
__device__ float g_final[(size_t)M_TOK*2*DIM];    // [seq | attn_out]
__device__ int   g_count[NJ];
__device__ int   g_rowlist[NJ*M_TOK];
__device__ unsigned int g_amask[M_TOK];

// ---------------- small kernels ----------------
__global__ void k_init() {
    int i = blockIdx.x*blockDim.x + threadIdx.x;
    if (i < V) { g_present[i] = 0; g_lastpos[i] = -1; }
    if (i < NJ) g_count[i] = 0;
    if (i < M_TOK) g_amask[i] = 0;
}

__global__ void k_scatter(const int* __restrict__ ids) {
    int s = threadIdx.x;                  // 512 threads
    atomicMax(&g_lastpos[ids[s]], s);
}

__global__ void k_fill(const int* __restrict__ ids, const float* __restrict__ seq) {
    int s = blockIdx.x;
    int id = ids[s];
    if (g_lastpos[id] != s) return;       // only last occurrence writes
    const float4* src = (const float4*)(seq + (size_t)s*DIM);
    float4* dst = (float4*)(g_table + (size_t)id*DIM);
    dst[threadIdx.x] = src[threadIdx.x];  // 192 threads * float4 = 768
    if (threadIdx.x == 0) g_present[id] = 1;
}

__global__ void k_reset(const int* __restrict__ ids) {
    g_lastpos[ids[threadIdx.x]] = -1;     // benign races: all write -1
}

__global__ void k_copy_seq(const float* __restrict__ seq) {
    int m = blockIdx.x;
    ((float4*)(g_rij + (size_t)m*KDIM))[threadIdx.x] =
        ((const float4*)(seq + (size_t)m*DIM))[threadIdx.x];
}

__global__ void k_emb(const int* __restrict__ nb, int mbase) {
    int sj = blockIdx.x;                  // S*J blocks
    int j = sj % NJ;
    int m = mbase + sj / NJ;
    const int* nbp = nb + (size_t)sj * NBK;
    int id0 = nbp[0], id1 = nbp[1], id2 = nbp[2], id3 = nbp[3];
    int p0 = g_present[id0], p1 = g_present[id1], p2 = g_present[id2], p3 = g_present[id3];
    int t = threadIdx.x;                  // 192 threads, float4 each
    float4 acc = make_float4(0.f,0.f,0.f,0.f);
    if (p0) { float4 v = ((const float4*)(g_table + (size_t)id0*DIM))[t]; acc.x+=v.x; acc.y+=v.y; acc.z+=v.z; acc.w+=v.w; }
    if (p1) { float4 v = ((const float4*)(g_table + (size_t)id1*DIM))[t]; acc.x+=v.x; acc.y+=v.y; acc.z+=v.z; acc.w+=v.w; }
    if (p2) { float4 v = ((const float4*)(g_table + (size_t)id2*DIM))[t]; acc.x+=v.x; acc.y+=v.y; acc.z+=v.z; acc.w+=v.w; }
    if (p3) { float4 v = ((const float4*)(g_table + (size_t)id3*DIM))[t]; acc.x+=v.x; acc.y+=v.y; acc.z+=v.z; acc.w+=v.w; }
    ((float4*)(g_rij + (size_t)m*KDIM + DIM + (size_t)j*DIM))[t] = acc;
    if (t == 0 && (p0 | p1 | p2 | p3)) {
        atomicOr(&g_amask[m], 1u << j);
        int idx = atomicAdd(&g_count[j], 1);
        g_rowlist[j*M_TOK + idx] = m;
    }
}

// ---------------- main gated-MLP GEMM (output-sparse, gathered rows per j) ----------------
__global__ __launch_bounds__(256) void k_main_gemm(const float* __restrict__ Wmlp,
                                                   const float* __restrict__ bmlp) {
    int j = blockIdx.z;
    int cnt = g_count[j];
    int m0 = blockIdx.x * BM;
    if (m0 >= cnt) return;
    int nbase = blockIdx.y * BN;
    int gbase = j*DIM + nbase;

    __shared__ int rows[BM];
    __shared__ float As[BK][BM+4];
    __shared__ float Bs[BK][BN+4];

    int t = threadIdx.x;
    if (t < BM) {
        int mi = m0 + t;
        rows[t] = (mi < cnt) ? g_rowlist[j*M_TOK + mi] : -1;
    }
    __syncthreads();

    int tx = t & 15;           // n group
    int ty = t >> 4;           // m group
    float acc[4][4];
    #pragma unroll
    for (int i=0;i<4;i++)
        #pragma unroll
        for (int q=0;q<4;q++) acc[i][q] = 0.f;

    int la_r = t >> 2;         // 0..63
    int la_k = (t & 3) * 4;    // 0,4,8,12
    int arow = rows[la_r];
    bool aval = (arow >= 0);
    const float* aptr = g_rij + (size_t)(aval ? arow : 0)*KDIM + la_k;
    const float* bptr = Wmlp + (size_t)(gbase + la_r)*KDIM + la_k;

    for (int k0 = 0; k0 < KDIM; k0 += BK) {
        float4 av = aval ? *(const float4*)(aptr + k0) : make_float4(0.f,0.f,0.f,0.f);
        float4 bv = *(const float4*)(bptr + k0);
        __syncthreads();
        As[la_k+0][la_r] = av.x; As[la_k+1][la_r] = av.y;
        As[la_k+2][la_r] = av.z; As[la_k+3][la_r] = av.w;
        Bs[la_k+0][la_r] = bv.x; Bs[la_k+1][la_r] = bv.y;
        Bs[la_k+2][la_r] = bv.z; Bs[la_k+3][la_r] = bv.w;
        __syncthreads();
        #pragma unroll
        for (int kk = 0; kk < BK; kk++) {
            float4 a0 = *(const float4*)&As[kk][ty*4];
            float4 b0 = *(const float4*)&Bs[kk][tx*4];
            float a[4] = {a0.x, a0.y, a0.z, a0.w};
            float b[4] = {b0.x, b0.y, b0.z, b0.w};
            #pragma unroll
            for (int i=0;i<4;i++)
                #pragma unroll
                for (int q=0;q<4;q++) acc[i][q] += a[i]*b[q];
        }
    }

    #pragma unroll
    for (int i=0;i<4;i++) {
        int mi = m0 + ty*4 + i;
        if (mi >= cnt) continue;
        int row = rows[ty*4 + i];
        const float* nrow = g_rij + (size_t)row*KDIM + DIM + gbase;
        float* crow = g_c + (size_t)row*GDIM + gbase;
        #pragma unroll
        for (int q=0;q<4;q++) {
            int n = tx*4 + q;
            float v = acc[i][q] + bmlp[gbase + n];
            v = 1.f / (1.f + expf(-v));           // sigmoid gate
            crow[n] = v * nrow[n];                // c = g * n_flat
        }
    }
}

// ---------------- per-token Luong attention + combined assembly ----------------
__global__ __launch_bounds__(256) void k_attn(const float* __restrict__ seq) {
    int m = blockIdx.x;
    __shared__ float sseq[DIM];
    __shared__ float sc[NJ];
    __shared__ float sw[NJ];
    int t = threadIdx.x;
    for (int d = t; d < DIM; d += 256) sseq[d] = seq[(size_t)m*DIM + d];
    unsigned mask = g_amask[m];
    __syncthreads();

    int w = t >> 5, lane = t & 31;
    for (int j = w; j < NJ; j += 8) {
        float p = 0.f;
        if (mask & (1u << j)) {
            const float* cj = g_c + (size_t)m*GDIM + (size_t)j*DIM;
            for (int d = lane; d < DIM; d += 32) p += sseq[d]*cj[d];
            #pragma unroll
            for (int o = 16; o; o >>= 1) p += __shfl_xor_sync(0xffffffffu, p, o);
        }
        if (lane == 0) sc[j] = p;                 // inactive j -> score exactly 0
    }
    __syncthreads();
    if (t == 0) {
        float mx = sc[0];
        #pragma unroll
        for (int j = 1; j < NJ; j++) mx = fmaxf(mx, sc[j]);
        float sum = 0.f;
        #pragma unroll
        for (int j = 0; j < NJ; j++) { float e = expf(sc[j]-mx); sw[j] = e; sum += e; }
        float inv = 1.f/sum;
        #pragma unroll
        for (int j = 0; j < NJ; j++) sw[j] *= inv;
    }
    __syncthreads();
    for (int d = t; d < DIM; d += 256) {
        float mix = 0.f;
        unsigned mm = mask;
        while (mm) {
            int j = __ffs(mm) - 1; mm &= mm - 1;
            mix += sw[j] * g_c[(size_t)m*GDIM + (size_t)j*DIM + d];
        }
        g_combined[(size_t)m*2*DIM + d]       = mix;       // [mix | seq]
        g_combined[(size_t)m*2*DIM + DIM + d] = sseq[d];
        g_final[(size_t)m*2*DIM + d]          = sseq[d];   // [seq | attn_out]
    }
}

// ---------------- attn_out GEMM: tanh(combined @ W_attn^T + b) ----------------
__global__ __launch_bounds__(256) void k_attnout(const float* __restrict__ Wattn,
                                                 const float* __restrict__ battn) {
    const int KD = 2*DIM;                         // 1536
    int m0 = blockIdx.x * BM;
    int nbase = blockIdx.y * BN;

    __shared__ float As[BK][BM+4];
    __shared__ float Bs[BK][BN+4];

    int t = threadIdx.x;
    int tx = t & 15, ty = t >> 4;
    float acc[4][4];
    #pragma unroll
    for (int i=0;i<4;i++)
        #pragma unroll
        for (int q=0;q<4;q++) acc[i][q] = 0.f;

    int la_r = t >> 2;
    int la_k = (t & 3) * 4;
    const float* aptr = g_combined + (size_t)(m0 + la_r)*KD + la_k;
    const float* bptr = Wattn + (size_t)(nbase + la_r)*KD + la_k;

    for (int k0 = 0; k0 < KD; k0 += BK) {
        float4 av = *(const float4*)(aptr + k0);
        float4 bv = *(const float4*)(bptr + k0);
        __syncthreads();
        As[la_k+0][la_r] = av.x; As[la_k+1][la_r] = av.y;
        As[la_k+2][la_r] = av.z; As[la_k+3][la_r] = av.w;
        Bs[la_k+0][la_r] = bv.x; Bs[la_k+1][la_r] = bv.y;
        Bs[la_k+2][la_r] = bv.z; Bs[la_k+3][la_r] = bv.w;
        __syncthreads();
        #pragma unroll
        for (int kk = 0; kk < BK; kk++) {
            float4 a0 = *(const float4*)&As[kk][ty*4];
            float4 b0 = *(const float4*)&Bs[kk][tx*4];
            float a[4] = {a0.x, a0.y, a0.z, a0.w};
            float b[4] = {b0.x, b0.y, b0.z, b0.w};
            #pragma unroll
            for (int i=0;i<4;i++)
                #pragma unroll
                for (int q=0;q<4;q++) acc[i][q] += a[i]*b[q];
        }
    }
    #pragma unroll
    for (int i=0;i<4;i++) {
        int m = m0 + ty*4 + i;
        #pragma unroll
        for (int q=0;q<4;q++) {
            int n = nbase + tx*4 + q;
            g_final[(size_t)m*KD + DIM + n] = tanhf(acc[i][q] + battn[n]);
        }
    }
}

// ---------------- classification head ----------------
__global__ void k_logits(const float* __restrict__ Wcls, const float* __restrict__ bcls,
                         float* __restrict__ out) {
    int m = blockIdx.x*8 + (threadIdx.x >> 5);
    int lane = threadIdx.x & 31;
    const float* f = g_final + (size_t)m*2*DIM;
    #pragma unroll
    for (int l = 0; l < NUM_LABELS; l++) {
        float p = 0.f;
        const float* wr = Wcls + (size_t)l*2*DIM;
        for (int d = lane; d < 2*DIM; d += 32) p += f[d]*wr[d];
        #pragma unroll
        for (int o = 16; o; o >>= 1) p += __shfl_xor_sync(0xffffffffu, p, o);
        if (lane == 0) out[m*NUM_LABELS + l] = p + bcls[l];
    }
}

// ---------------- launch ----------------
extern "C" void kernel_launch(void* const* d_in, const int* in_sizes, int n_in,
                              void* d_out, int out_size) {
    const float* seq   = (const float*)d_in[0];
    const int*   ids   = (const int*)  d_in[1];
    const int*   nb    = (const int*)  d_in[2];
    const float* Wmlp  = (const float*)d_in[3];
    const float* bmlp  = (const float*)d_in[4];
    const float* Wattn = (const float*)d_in[5];
    const float* battn = (const float*)d_in[6];
    const float* Wcls  = (const float*)d_in[7];
    const float* bcls  = (const float*)d_in[8];
    float* out = (float*)d_out;

    k_init<<<(V+255)/256, 256>>>();
    k_copy_seq<<<M_TOK, 192>>>(seq);
    for (int b = 0; b < NBATCH; b++) {
        k_scatter<<<1, SLEN>>>(ids + b*SLEN);
        k_fill<<<SLEN, 192>>>(ids + b*SLEN, seq + (size_t)b*SLEN*DIM);
        k_emb<<<SLEN*NJ, 192>>>(nb + (size_t)b*SLEN*NJ*NBK, b*SLEN);
        if (b + 1 < NBATCH) k_reset<<<1, SLEN>>>(ids + b*SLEN);
    }
    dim3 gg(M_TOK/BM, DIM/BN, NJ);     // (16, 12, 12); most blocks exit (output sparsity)
    k_main_gemm<<<gg, 256>>>(Wmlp, bmlp);
    k_attn<<<M_TOK, 256>>>(seq);
    dim3 ga(M_TOK/BM, DIM/BN);         // (16, 12)
    k_attnout<<<ga, 256>>>(Wattn, battn);
    k_logits<<<M_TOK/8, 256>>>(Wcls, bcls, out);
}

// round 2
// speedup vs baseline: 2.5372x; 2.5372x over previous
#include <cuda_runtime.h>
#include <math.h>

#define V 30522
#define NBATCH 2
#define SLEN 512
#define DIM 768
#define NJ 12
#define NBK 4
#define NUM_LABELS 7
#define M_TOK (NBATCH*SLEN)   /* 1024 */
#define KDIM (13*DIM)         /* 9984 */
#define GDIM (NJ*DIM)         /* 9216 */
#define NPAIR (NJ*13)         /* 156 pair lists: pid = j*13 + chunk */

// ---------------- scratch (device globals; no allocation allowed) ----------------
__device__ float g_table[(size_t)V*DIM];
__device__ int   g_present[V];
__device__ int   g_lastpos[V];
__device__ float g_rij[(size_t)M_TOK*KDIM];       // [seq | n_flat]
__device__ float g_pre[(size_t)M_TOK*GDIM];       // pre-sigmoid gate accumulator
__device__ float g_c[(size_t)M_TOK*GDIM];         // gated neighbors
__device__ float g_combined[(size_t)M_TOK*2*DIM]; // [mix | seq]
__device__ float g_final[(size_t)M_TOK*2*DIM];    // [seq | attn_out]
__device__ unsigned int g_amask[M_TOK];
__device__ int   g_pcount[NPAIR];
__device__ int   g_plist[NPAIR*M_TOK];

// ---------------- f32x2 helpers ----------------
__device__ __forceinline__ unsigned long long pk2(float x) {
    unsigned long long r; asm("mov.b64 %0, {%1, %1};" : "=l"(r) : "f"(x)); return r;
}
__device__ __forceinline__ void fma2(unsigned long long &d, unsigned long long a, unsigned long long b) {
    asm("fma.rn.f32x2 %0, %1, %2, %0;" : "+l"(d) : "l"(a), "l"(b));
}
__device__ __forceinline__ float2 up2(unsigned long long v) {
    float2 r; asm("mov.b64 {%0, %1}, %2;" : "=f"(r.x), "=f"(r.y) : "l"(v)); return r;
}

// ---------------- small kernels ----------------
__global__ void k_init() {
    int i = blockIdx.x*blockDim.x + threadIdx.x;
    if (i < V) { g_present[i] = 0; g_lastpos[i] = -1; }
    if (i < NPAIR) g_pcount[i] = 0;
    if (i < M_TOK) g_amask[i] = 0;
}

__global__ void k_scatter(const int* __restrict__ ids) {
    atomicMax(&g_lastpos[ids[threadIdx.x]], (int)threadIdx.x);
}

__global__ void k_fill(const int* __restrict__ ids, const float* __restrict__ seq) {
    int s = blockIdx.x;
    int id = ids[s];
    if (g_lastpos[id] != s) return;
    const float4* src = (const float4*)(seq + (size_t)s*DIM);
    float4* dst = (float4*)(g_table + (size_t)id*DIM);
    dst[threadIdx.x] = src[threadIdx.x];
    if (threadIdx.x == 0) g_present[id] = 1;
}

__global__ void k_reset(const int* __restrict__ ids) {
    g_lastpos[ids[threadIdx.x]] = -1;
}

__global__ void k_copy_seq(const float* __restrict__ seq) {
    int m = blockIdx.x;
    ((float4*)(g_rij + (size_t)m*KDIM))[threadIdx.x] =
        ((const float4*)(seq + (size_t)m*DIM))[threadIdx.x];
}

__global__ void k_emb(const int* __restrict__ nb, int mbase) {
    int sj = blockIdx.x;
    int j = sj % NJ;
    int m = mbase + sj / NJ;
    const int* nbp = nb + (size_t)sj * NBK;
    int id0 = nbp[0], id1 = nbp[1], id2 = nbp[2], id3 = nbp[3];
    int p0 = g_present[id0], p1 = g_present[id1], p2 = g_present[id2], p3 = g_present[id3];
    int t = threadIdx.x;
    float4 acc = make_float4(0.f,0.f,0.f,0.f);
    if (p0) { float4 v = ((const float4*)(g_table + (size_t)id0*DIM))[t]; acc.x+=v.x; acc.y+=v.y; acc.z+=v.z; acc.w+=v.w; }
    if (p1) { float4 v = ((const float4*)(g_table + (size_t)id1*DIM))[t]; acc.x+=v.x; acc.y+=v.y; acc.z+=v.z; acc.w+=v.w; }
    if (p2) { float4 v = ((const float4*)(g_table + (size_t)id2*DIM))[t]; acc.x+=v.x; acc.y+=v.y; acc.z+=v.z; acc.w+=v.w; }
    if (p3) { float4 v = ((const float4*)(g_table + (size_t)id3*DIM))[t]; acc.x+=v.x; acc.y+=v.y; acc.z+=v.z; acc.w+=v.w; }
    ((float4*)(g_rij + (size_t)m*KDIM + DIM + (size_t)j*DIM))[t] = acc;
    if (t == 0 && (p0 | p1 | p2 | p3)) atomicOr(&g_amask[m], 1u << j);
}

// build per-(jout, chunk) row lists from masks
__global__ void k_pairs() {
    int m = blockIdx.x*256 + threadIdx.x;
    if (m >= M_TOK) return;
    unsigned mask = g_amask[m];
    if (!mask) return;
    unsigned mm = mask;
    while (mm) {
        int j = __ffs(mm) - 1; mm &= mm - 1;
        int base = j*13;
        int idx = atomicAdd(&g_pcount[base], 1);
        g_plist[base*M_TOK + idx] = m;
        unsigned m2 = mask;
        while (m2) {
            int c = __ffs(m2) - 1; m2 &= m2 - 1;
            int p = base + 1 + c;
            int idx2 = atomicAdd(&g_pcount[p], 1);
            g_plist[p*M_TOK + idx2] = m;
        }
    }
}

// ---------------- sparse pair GEMM: tile 32x128, BK=16, 128 threads ----------------
template<bool ATOMIC>
__global__ __launch_bounds__(128) void k_pair_gemm(const float* __restrict__ Wmlp,
                                                   const float* __restrict__ bmlp) {
    int jout, chunk, pid;
    if (!ATOMIC) { jout = blockIdx.z; chunk = 0; pid = jout*13; }
    else { jout = blockIdx.z / 12; int cc = blockIdx.z % 12; chunk = cc + 1; pid = jout*13 + 1 + cc; }
    int cnt = g_pcount[pid];
    if (cnt == 0) return;
    int nbase = blockIdx.y * 128;
    const int* list = g_plist + pid*M_TOK;

    __shared__ float As[16][36];
    __shared__ float Bs[16][132];
    __shared__ int rows[32];

    int t = threadIdx.x;
    int tx = t & 15, ty = t >> 4;
    int lr = t >> 2, lk = (t & 3) * 4;

    // B row pointers (fixed across m-tiles)
    const float* bp[4];
    #pragma unroll
    for (int it = 0; it < 4; it++)
        bp[it] = Wmlp + (size_t)(jout*768 + nbase + lr + 32*it)*KDIM + chunk*768 + lk;

    float bias[8];
    if (!ATOMIC) {
        #pragma unroll
        for (int q = 0; q < 8; q++) bias[q] = bmlp[jout*768 + nbase + tx*8 + q];
    }

    for (int mt = blockIdx.x; mt*32 < cnt; mt += gridDim.x) {
        int m0 = mt*32;
        __syncthreads();
        if (t < 32) rows[t] = (m0 + t < cnt) ? list[m0 + t] : -1;
        __syncthreads();

        int arow = rows[lr];
        const float* aptr = g_rij + (size_t)(arow < 0 ? 0 : arow)*KDIM + chunk*768 + lk;

        unsigned long long acc[4][4];
        #pragma unroll
        for (int i = 0; i < 4; i++)
            #pragma unroll
            for (int q = 0; q < 4; q++) acc[i][q] = 0ull;

        for (int k0 = 0; k0 < 768; k0 += 16) {
            float4 av = (arow >= 0) ? *(const float4*)(aptr + k0) : make_float4(0.f,0.f,0.f,0.f);
            float4 bv[4];
            #pragma unroll
            for (int it = 0; it < 4; it++) bv[it] = *(const float4*)(bp[it] + k0);
            __syncthreads();
            As[lk+0][lr] = av.x; As[lk+1][lr] = av.y; As[lk+2][lr] = av.z; As[lk+3][lr] = av.w;
            #pragma unroll
            for (int it = 0; it < 4; it++) {
                int rr = lr + 32*it;
                Bs[lk+0][rr] = bv[it].x; Bs[lk+1][rr] = bv[it].y;
                Bs[lk+2][rr] = bv[it].z; Bs[lk+3][rr] = bv[it].w;
            }
            __syncthreads();
            #pragma unroll
            for (int kk = 0; kk < 16; kk++) {
                float4 a = *(const float4*)&As[kk][ty*4];
                ulonglong2 b01 = *(const ulonglong2*)&Bs[kk][tx*8];
                ulonglong2 b23 = *(const ulonglong2*)&Bs[kk][tx*8 + 4];
                unsigned long long a0 = pk2(a.x), a1 = pk2(a.y), a2 = pk2(a.z), a3 = pk2(a.w);
                fma2(acc[0][0], a0, b01.x); fma2(acc[0][1], a0, b01.y);
                fma2(acc[0][2], a0, b23.x); fma2(acc[0][3], a0, b23.y);
                fma2(acc[1][0], a1, b01.x); fma2(acc[1][1], a1, b01.y);
                fma2(acc[1][2], a1, b23.x); fma2(acc[1][3], a1, b23.y);
                fma2(acc[2][0], a2, b01.x); fma2(acc[2][1], a2, b01.y);
                fma2(acc[2][2], a2, b23.x); fma2(acc[2][3], a2, b23.y);
                fma2(acc[3][0], a3, b01.x); fma2(acc[3][1], a3, b01.y);
                fma2(acc[3][2], a3, b23.x); fma2(acc[3][3], a3, b23.y);
            }
        }

        #pragma unroll
        for (int i = 0; i < 4; i++) {
            int mi = m0 + ty*4 + i;
            if (mi >= cnt) continue;
            int row = rows[ty*4 + i];
            float* dst = g_pre + (size_t)row*GDIM + jout*768 + nbase + tx*8;
            #pragma unroll
            for (int qh = 0; qh < 4; qh++) {
                float2 v = up2(acc[i][qh]);
                if (ATOMIC) {
                    atomicAdd(dst + 2*qh,     v.x);
                    atomicAdd(dst + 2*qh + 1, v.y);
                } else {
                    dst[2*qh]     = v.x + bias[2*qh];
                    dst[2*qh + 1] = v.y + bias[2*qh + 1];
                }
            }
        }
    }
}

// ---------------- gate epilogue: c = sigmoid(pre) * n for active (m,j) ----------------
__global__ __launch_bounds__(256) void k_gate() {
    int j = blockIdx.x;
    int cnt = g_pcount[j*13];
    const int* list = g_plist + (j*13)*M_TOK;
    int t = threadIdx.x;
    for (int idx = blockIdx.y; idx < cnt; idx += gridDim.y) {
        int row = list[idx];
        const float* pre = g_pre + (size_t)row*GDIM + j*768;
        const float* nf  = g_rij + (size_t)row*KDIM + (1 + j)*768;
        float* cc = g_c + (size_t)row*GDIM + j*768;
        #pragma unroll
        for (int d = t; d < 768; d += 256) {
            float s = 1.f / (1.f + expf(-pre[d]));
            cc[d] = s * nf[d];
        }
    }
}

// ---------------- per-token Luong attention + combined assembly ----------------
__global__ __launch_bounds__(256) void k_attn(const float* __restrict__ seq) {
    int m = blockIdx.x;
    __shared__ float sseq[DIM];
    __shared__ float sc[NJ];
    __shared__ float sw[NJ];
    int t = threadIdx.x;
    for (int d = t; d < DIM; d += 256) sseq[d] = seq[(size_t)m*DIM + d];
    unsigned mask = g_amask[m];
    __syncthreads();

    int w = t >> 5, lane = t & 31;
    for (int j = w; j < NJ; j += 8) {
        float p = 0.f;
        if (mask & (1u << j)) {
            const float* cj = g_c + (size_t)m*GDIM + (size_t)j*DIM;
            for (int d = lane; d < DIM; d += 32) p += sseq[d]*cj[d];
            #pragma unroll
            for (int o = 16; o; o >>= 1) p += __shfl_xor_sync(0xffffffffu, p, o);
        }
        if (lane == 0) sc[j] = p;
    }
    __syncthreads();
    if (t == 0) {
        float mx = sc[0];
        #pragma unroll
        for (int j = 1; j < NJ; j++) mx = fmaxf(mx, sc[j]);
        float sum = 0.f;
        #pragma unroll
        for (int j = 0; j < NJ; j++) { float e = expf(sc[j]-mx); sw[j] = e; sum += e; }
        float inv = 1.f/sum;
        #pragma unroll
        for (int j = 0; j < NJ; j++) sw[j] *= inv;
    }
    __syncthreads();
    for (int d = t; d < DIM; d += 256) {
        float mix = 0.f;
        unsigned mm = mask;
        while (mm) {
            int j = __ffs(mm) - 1; mm &= mm - 1;
            mix += sw[j] * g_c[(size_t)m*GDIM + (size_t)j*DIM + d];
        }
        g_combined[(size_t)m*2*DIM + d]       = mix;
        g_combined[(size_t)m*2*DIM + DIM + d] = sseq[d];
        g_final[(size_t)m*2*DIM + d]          = sseq[d];
    }
}

// ---------------- attn_out GEMM: tanh(combined @ W_attn^T + b), 32x128 tiles ----------------
__global__ __launch_bounds__(128) void k_attnout2(const float* __restrict__ Wattn,
                                                  const float* __restrict__ battn) {
    const int KD = 2*DIM; // 1536
    int m0 = blockIdx.x * 32;
    int nbase = blockIdx.y * 128;

    __shared__ float As[16][36];
    __shared__ float Bs[16][132];

    int t = threadIdx.x;
    int tx = t & 15, ty = t >> 4;
    int lr = t >> 2, lk = (t & 3) * 4;

    const float* aptr = g_combined + (size_t)(m0 + lr)*KD + lk;
    const float* bp[4];
    #pragma unroll
    for (int it = 0; it < 4; it++)
        bp[it] = Wattn + (size_t)(nbase + lr + 32*it)*KD + lk;

    unsigned long long acc[4][4];
    #pragma unroll
    for (int i = 0; i < 4; i++)
        #pragma unroll
        for (int q = 0; q < 4; q++) acc[i][q] = 0ull;

    for (int k0 = 0; k0 < KD; k0 += 16) {
        float4 av = *(const float4*)(aptr + k0);
        float4 bv[4];
        #pragma unroll
        for (int it = 0; it < 4; it++) bv[it] = *(const float4*)(bp[it] + k0);
        __syncthreads();
        As[lk+0][lr] = av.x; As[lk+1][lr] = av.y; As[lk+2][lr] = av.z; As[lk+3][lr] = av.w;
        #pragma unroll
        for (int it = 0; it < 4; it++) {
            int rr = lr + 32*it;
            Bs[lk+0][rr] = bv[it].x; Bs[lk+1][rr] = bv[it].y;
            Bs[lk+2][rr] = bv[it].z; Bs[lk+3][rr] = bv[it].w;
        }
        __syncthreads();
        #pragma unroll
        for (int kk = 0; kk < 16; kk++) {
            float4 a = *(const float4*)&As[kk][ty*4];
            ulonglong2 b01 = *(const ulonglong2*)&Bs[kk][tx*8];
            ulonglong2 b23 = *(const ulonglong2*)&Bs[kk][tx*8 + 4];
            unsigned long long a0 = pk2(a.x), a1 = pk2(a.y), a2 = pk2(a.z), a3 = pk2(a.w);
            fma2(acc[0][0], a0, b01.x); fma2(acc[0][1], a0, b01.y);
            fma2(acc[0][2], a0, b23.x); fma2(acc[0][3], a0, b23.y);
            fma2(acc[1][0], a1, b01.x); fma2(acc[1][1], a1, b01.y);
            fma2(acc[1][2], a1, b23.x); fma2(acc[1][3], a1, b23.y);
            fma2(acc[2][0], a2, b01.x); fma2(acc[2][1], a2, b01.y);
            fma2(acc[2][2], a2, b23.x); fma2(acc[2][3], a2, b23.y);
            fma2(acc[3][0], a3, b01.x); fma2(acc[3][1], a3, b01.y);
            fma2(acc[3][2], a3, b23.x); fma2(acc[3][3], a3, b23.y);
        }
    }

    #pragma unroll
    for (int i = 0; i < 4; i++) {
        int m = m0 + ty*4 + i;
        float* dst = g_final + (size_t)m*KD + DIM + nbase + tx*8;
        #pragma unroll
        for (int qh = 0; qh < 4; qh++) {
            float2 v = up2(acc[i][qh]);
            int n = nbase + tx*8 + 2*qh;
            dst[2*qh]     = tanhf(v.x + battn[n]);
            dst[2*qh + 1] = tanhf(v.y + battn[n + 1]);
        }
    }
}

// ---------------- classification head ----------------
__global__ void k_logits(const float* __restrict__ Wcls, const float* __restrict__ bcls,
                         float* __restrict__ out) {
    int m = blockIdx.x*8 + (threadIdx.x >> 5);
    int lane = threadIdx.x & 31;
    const float* f = g_final + (size_t)m*2*DIM;
    #pragma unroll
    for (int l = 0; l < NUM_LABELS; l++) {
        float p = 0.f;
        const float* wr = Wcls + (size_t)l*2*DIM;
        for (int d = lane; d < 2*DIM; d += 32) p += f[d]*wr[d];
        #pragma unroll
        for (int o = 16; o; o >>= 1) p += __shfl_xor_sync(0xffffffffu, p, o);
        if (lane == 0) out[m*NUM_LABELS + l] = p + bcls[l];
    }
}

// ---------------- launch ----------------
extern "C" void kernel_launch(void* const* d_in, const int* in_sizes, int n_in,
                              void* d_out, int out_size) {
    const float* seq   = (const float*)d_in[0];
    const int*   ids   = (const int*)  d_in[1];
    const int*   nb    = (const int*)  d_in[2];
    const float* Wmlp  = (const float*)d_in[3];
    const float* bmlp  = (const float*)d_in[4];
    const float* Wattn = (const float*)d_in[5];
    const float* battn = (const float*)d_in[6];
    const float* Wcls  = (const float*)d_in[7];
    const float* bcls  = (const float*)d_in[8];
    float* out = (float*)d_out;

    k_init<<<(V+255)/256, 256>>>();
    k_copy_seq<<<M_TOK, 192>>>(seq);
    for (int b = 0; b < NBATCH; b++) {
        k_scatter<<<1, SLEN>>>(ids + b*SLEN);
        k_fill<<<SLEN, 192>>>(ids + b*SLEN, seq + (size_t)b*SLEN*DIM);
        k_emb<<<SLEN*NJ, 192>>>(nb + (size_t)b*SLEN*NJ*NBK, b*SLEN);
        if (b + 1 < NBATCH) k_reset<<<1, SLEN>>>(ids + b*SLEN);
    }
    k_pairs<<<(M_TOK+255)/256, 256>>>();
    dim3 ga(8, 6, NJ);              // pass A: chunk 0 (seq), stores + bias
    k_pair_gemm<false><<<ga, 128>>>(Wmlp, bmlp);
    dim3 gb(2, 6, NJ*NJ);           // pass B: chunks 1..12, atomic accumulate
    k_pair_gemm<true><<<gb, 128>>>(Wmlp, bmlp);
    dim3 gg(NJ, 16);
    k_gate<<<gg, 256>>>();
    k_attn<<<M_TOK, 256>>>(seq);
    dim3 go(M_TOK/32, 6);
    k_attnout2<<<go, 128>>>(Wattn, battn);
    k_logits<<<M_TOK/8, 256>>>(Wcls, bcls, out);
}

// round 4
// speedup vs baseline: 5.8625x; 2.3106x over previous
#include <cuda_runtime.h>
#include <cstdint>
#include <math.h>

#define V 30522
#define NBATCH 2
#define SLEN 512
#define DIM 768
#define NJ 12
#define NBK 4
#define NUM_LABELS 7
#define M_TOK (NBATCH*SLEN)   /* 1024 */
#define KDIM (13*DIM)         /* 9984 */
#define GDIM (NJ*DIM)         /* 9216 */
#define NPAIR (NJ*13)         /* 156 */

#define ROWP 36               /* padded smem row length (floats) for BK=32 */
#define STAGE_F (2*128*ROWP)  /* floats per stage (A + B) */
#define SMEM_BYTES (2*STAGE_F*4)

// ---------------- scratch ----------------
__device__ float g_table[(size_t)V*DIM];
__device__ int   g_present[V];
__device__ int   g_lastpos[V];
__device__ float g_rij[(size_t)M_TOK*KDIM];       // [seq | n_flat]
__device__ float g_pre[(size_t)M_TOK*GDIM];       // pre-sigmoid gate
__device__ float g_c[(size_t)M_TOK*GDIM];
__device__ float g_combined[(size_t)M_TOK*2*DIM];
__device__ float g_final[(size_t)M_TOK*2*DIM];
__device__ unsigned int g_amask[M_TOK];
__device__ int   g_pcount[NPAIR];
__device__ int   g_plist[NPAIR*M_TOK];

// ---------------- helpers ----------------
__device__ __forceinline__ uint32_t smem_u32(const void* p) {
    uint32_t a; asm("{ .reg .u64 t; cvta.to.shared.u64 t, %1; cvt.u32.u64 %0, t; }" : "=r"(a) : "l"(p));
    return a;
}
__device__ __forceinline__ void cp16(uint32_t saddr, const void* g) {
    asm volatile("cp.async.ca.shared.global [%0], [%1], 16;" :: "r"(saddr), "l"(g));
}
#define CP_COMMIT() asm volatile("cp.async.commit_group;" ::: "memory")
#define CP_WAIT1()  asm volatile("cp.async.wait_group 1;" ::: "memory")

__device__ __forceinline__ void mma_tf32(float* c, const uint32_t* a, const uint32_t* b) {
    asm volatile("mma.sync.aligned.m16n8k8.row.col.f32.tf32.tf32.f32 "
                 "{%0,%1,%2,%3}, {%4,%5,%6,%7}, {%8,%9}, {%0,%1,%2,%3};"
                 : "+f"(c[0]), "+f"(c[1]), "+f"(c[2]), "+f"(c[3])
                 : "r"(a[0]), "r"(a[1]), "r"(a[2]), "r"(a[3]), "r"(b[0]), "r"(b[1]));
}

// ---------------- small kernels ----------------
__global__ void k_init() {
    int i = blockIdx.x*blockDim.x + threadIdx.x;
    if (i < V) { g_present[i] = 0; g_lastpos[i] = -1; }
    if (i < NPAIR) g_pcount[i] = 0;
    if (i < M_TOK) g_amask[i] = 0;
}
__global__ void k_scatter(const int* __restrict__ ids) {
    atomicMax(&g_lastpos[ids[threadIdx.x]], (int)threadIdx.x);
}
__global__ void k_fill(const int* __restrict__ ids, const float* __restrict__ seq) {
    int s = blockIdx.x;
    int id = ids[s];
    if (g_lastpos[id] != s) return;
    const float4* src = (const float4*)(seq + (size_t)s*DIM);
    float4* dst = (float4*)(g_table + (size_t)id*DIM);
    dst[threadIdx.x] = src[threadIdx.x];
    if (threadIdx.x == 0) g_present[id] = 1;
}
__global__ void k_reset(const int* __restrict__ ids) {
    g_lastpos[ids[threadIdx.x]] = -1;
}
__global__ void k_copy_seq(const float* __restrict__ seq) {
    int m = blockIdx.x;
    ((float4*)(g_rij + (size_t)m*KDIM))[threadIdx.x] =
        ((const float4*)(seq + (size_t)m*DIM))[threadIdx.x];
}
__global__ void k_emb(const int* __restrict__ nb, int mbase) {
    int sj = blockIdx.x;
    int j = sj % NJ;
    int m = mbase + sj / NJ;
    const int* nbp = nb + (size_t)sj * NBK;
    int id0 = nbp[0], id1 = nbp[1], id2 = nbp[2], id3 = nbp[3];
    int p0 = g_present[id0], p1 = g_present[id1], p2 = g_present[id2], p3 = g_present[id3];
    int t = threadIdx.x;
    float4 acc = make_float4(0.f,0.f,0.f,0.f);
    if (p0) { float4 v = ((const float4*)(g_table + (size_t)id0*DIM))[t]; acc.x+=v.x; acc.y+=v.y; acc.z+=v.z; acc.w+=v.w; }
    if (p1) { float4 v = ((const float4*)(g_table + (size_t)id1*DIM))[t]; acc.x+=v.x; acc.y+=v.y; acc.z+=v.z; acc.w+=v.w; }
    if (p2) { float4 v = ((const float4*)(g_table + (size_t)id2*DIM))[t]; acc.x+=v.x; acc.y+=v.y; acc.z+=v.z; acc.w+=v.w; }
    if (p3) { float4 v = ((const float4*)(g_table + (size_t)id3*DIM))[t]; acc.x+=v.x; acc.y+=v.y; acc.z+=v.z; acc.w+=v.w; }
    ((float4*)(g_rij + (size_t)m*KDIM + DIM + (size_t)j*DIM))[t] = acc;
    if (t == 0 && (p0 | p1 | p2 | p3)) atomicOr(&g_amask[m], 1u << j);
}
__global__ void k_pairs() {
    int m = blockIdx.x*256 + threadIdx.x;
    if (m >= M_TOK) return;
    unsigned mask = g_amask[m];
    if (!mask) return;
    unsigned mm = mask;
    while (mm) {
        int j = __ffs(mm) - 1; mm &= mm - 1;
        int base = j*13;
        int idx = atomicAdd(&g_pcount[base], 1);
        g_plist[base*M_TOK + idx] = m;
        unsigned m2 = mask;
        while (m2) {
            int c = __ffs(m2) - 1; m2 &= m2 - 1;
            int p = base + 1 + c;
            int idx2 = atomicAdd(&g_pcount[p], 1);
            g_plist[p*M_TOK + idx2] = m;
        }
    }
}

// ============ core 128x128 tf32 mma block compute (shared by all GEMMs) ============
// As[m][ROWP], Bs[n][ROWP] per stage, NS stages of BK=32.
// acc[2][8][4]; warp layout: wm = wid&3 (32 rows), wn = wid>>2 (64 cols).
struct MmaCtx {
    float acc[2][8][4];
};

__device__ __forceinline__ void mma_stage(const uint32_t* sbase, int wm, int wn,
                                          int gid, int tig, MmaCtx& ctx) {
    const uint32_t* As = sbase;
    const uint32_t* Bs = sbase + 128*ROWP;
    #pragma unroll
    for (int ks = 0; ks < 4; ks++) {
        uint32_t a[2][4], b[8][2];
        #pragma unroll
        for (int mt = 0; mt < 2; mt++) {
            int r0 = wm*32 + mt*16 + gid;
            a[mt][0] = As[r0*ROWP + ks*8 + tig];
            a[mt][1] = As[(r0+8)*ROWP + ks*8 + tig];
            a[mt][2] = As[r0*ROWP + ks*8 + tig + 4];
            a[mt][3] = As[(r0+8)*ROWP + ks*8 + tig + 4];
        }
        #pragma unroll
        for (int nt = 0; nt < 8; nt++) {
            int n = wn*64 + nt*8 + gid;
            b[nt][0] = Bs[n*ROWP + ks*8 + tig];
            b[nt][1] = Bs[n*ROWP + ks*8 + tig + 4];
        }
        #pragma unroll
        for (int mt = 0; mt < 2; mt++)
            #pragma unroll
            for (int nt = 0; nt < 8; nt++)
                mma_tf32(ctx.acc[mt][nt], a[mt], b[nt]);
    }
}

// ---------------- sparse pair GEMM (tensor cores) ----------------
template<bool ATOMIC>
__global__ __launch_bounds__(256) void k_mma_gemm(const float* __restrict__ Wmlp,
                                                  const float* __restrict__ bmlp) {
    int jout, chunk, pid;
    if (!ATOMIC) { jout = blockIdx.z; chunk = 0; pid = jout*13; }
    else { jout = blockIdx.z / 12; int cc = blockIdx.z % 12; chunk = cc + 1; pid = jout*13 + 1 + cc; }
    int cnt = g_pcount[pid];
    int m0 = blockIdx.x * 128;
    if (m0 >= cnt) return;
    int nbase = blockIdx.y * 128;

    extern __shared__ float smem[];
    __shared__ int rows_sh[128];
    uint32_t sb = smem_u32(smem);
    int tid = threadIdx.x;
    int wid = tid >> 5, lane = tid & 31;
    int gid = lane >> 2, tig = lane & 3;
    int wm = wid & 3, wn = wid >> 2;

    if (tid < 128) {
        int mi = m0 + tid;
        rows_sh[tid] = (mi < cnt) ? g_plist[pid*M_TOK + mi] : -1;
    }
    __syncthreads();

    // per-thread cp.async assignments: 4 A segs + 4 B segs
    const float* aptr[4]; const float* bptr[4];
    uint32_t sa[4], sbb[4];
    #pragma unroll
    for (int i = 0; i < 4; i++) {
        int idx = i*256 + tid;           // 0..1023
        int row = idx >> 3, seg = idx & 7;
        int arow = rows_sh[row];
        aptr[i] = g_rij + (size_t)(arow < 0 ? 0 : arow)*KDIM + chunk*768 + seg*4;
        bptr[i] = Wmlp + (size_t)(jout*768 + nbase + row)*KDIM + chunk*768 + seg*4;
        sa[i]  = sb + (row*ROWP + seg*4)*4;
        sbb[i] = sb + ((128*ROWP) + row*ROWP + seg*4)*4;
    }

    const int NS = 24;
    // prologue: stages 0,1
    #pragma unroll
    for (int s = 0; s < 2; s++) {
        uint32_t so = s*STAGE_F*4;
        #pragma unroll
        for (int i = 0; i < 4; i++) {
            cp16(sa[i] + so,  aptr[i] + s*32);
            cp16(sbb[i] + so, bptr[i] + s*32);
        }
        CP_COMMIT();
    }

    MmaCtx ctx;
    #pragma unroll
    for (int mt = 0; mt < 2; mt++)
        #pragma unroll
        for (int nt = 0; nt < 8; nt++)
            #pragma unroll
            for (int q = 0; q < 4; q++) ctx.acc[mt][nt][q] = 0.f;

    for (int s = 0; s < NS; s++) {
        CP_WAIT1();
        __syncthreads();
        mma_stage((const uint32_t*)smem + (s & 1)*STAGE_F, wm, wn, gid, tig, ctx);
        __syncthreads();
        if (s + 2 < NS) {
            uint32_t so = ((s + 2) & 1)*STAGE_F*4;
            #pragma unroll
            for (int i = 0; i < 4; i++) {
                cp16(sa[i] + so,  aptr[i] + (s + 2)*32);
                cp16(sbb[i] + so, bptr[i] + (s + 2)*32);
            }
        }
        CP_COMMIT();
    }

    // epilogue
    #pragma unroll
    for (int mt = 0; mt < 2; mt++) {
        #pragma unroll
        for (int half = 0; half < 2; half++) {
            int lr = wm*32 + mt*16 + gid + half*8;
            int row = rows_sh[lr];
            if (row < 0) continue;
            float* dst = g_pre + (size_t)row*GDIM + jout*768 + nbase;
            #pragma unroll
            for (int nt = 0; nt < 8; nt++) {
                int n = wn*64 + nt*8 + 2*tig;
                float v0 = ctx.acc[mt][nt][half*2 + 0];
                float v1 = ctx.acc[mt][nt][half*2 + 1];
                if (ATOMIC) {
                    atomicAdd(&dst[n], v0);
                    atomicAdd(&dst[n+1], v1);
                } else {
                    int gcol = jout*768 + nbase + n;
                    dst[n]   = v0 + bmlp[gcol];
                    dst[n+1] = v1 + bmlp[gcol+1];
                }
            }
        }
    }
}

// ---------------- attn_out GEMM: tanh(combined @ Wattn^T + b) ----------------
__global__ __launch_bounds__(256) void k_attnout_mma(const float* __restrict__ Wattn,
                                                     const float* __restrict__ battn) {
    const int KD = 2*DIM; // 1536
    int m0 = blockIdx.x * 128;
    int nbase = blockIdx.y * 128;

    extern __shared__ float smem[];
    uint32_t sb = smem_u32(smem);
    int tid = threadIdx.x;
    int wid = tid >> 5, lane = tid & 31;
    int gid = lane >> 2, tig = lane & 3;
    int wm = wid & 3, wn = wid >> 2;

    const float* aptr[4]; const float* bptr[4];
    uint32_t sa[4], sbb[4];
    #pragma unroll
    for (int i = 0; i < 4; i++) {
        int idx = i*256 + tid;
        int row = idx >> 3, seg = idx & 7;
        aptr[i] = g_combined + (size_t)(m0 + row)*KD + seg*4;
        bptr[i] = Wattn + (size_t)(nbase + row)*KD + seg*4;
        sa[i]  = sb + (row*ROWP + seg*4)*4;
        sbb[i] = sb + ((128*ROWP) + row*ROWP + seg*4)*4;
    }

    const int NS = 48;
    #pragma unroll
    for (int s = 0; s < 2; s++) {
        uint32_t so = s*STAGE_F*4;
        #pragma unroll
        for (int i = 0; i < 4; i++) {
            cp16(sa[i] + so,  aptr[i] + s*32);
            cp16(sbb[i] + so, bptr[i] + s*32);
        }
        CP_COMMIT();
    }

    MmaCtx ctx;
    #pragma unroll
    for (int mt = 0; mt < 2; mt++)
        #pragma unroll
        for (int nt = 0; nt < 8; nt++)
            #pragma unroll
            for (int q = 0; q < 4; q++) ctx.acc[mt][nt][q] = 0.f;

    for (int s = 0; s < NS; s++) {
        CP_WAIT1();
        __syncthreads();
        mma_stage((const uint32_t*)smem + (s & 1)*STAGE_F, wm, wn, gid, tig, ctx);
        __syncthreads();
        if (s + 2 < NS) {
            uint32_t so = ((s + 2) & 1)*STAGE_F*4;
            #pragma unroll
            for (int i = 0; i < 4; i++) {
                cp16(sa[i] + so,  aptr[i] + (s + 2)*32);
                cp16(sbb[i] + so, bptr[i] + (s + 2)*32);
            }
        }
        CP_COMMIT();
    }

    #pragma unroll
    for (int mt = 0; mt < 2; mt++) {
        #pragma unroll
        for (int half = 0; half < 2; half++) {
            int m = m0 + wm*32 + mt*16 + gid + half*8;
            float* dst = g_final + (size_t)m*KD + DIM;
            #pragma unroll
            for (int nt = 0; nt < 8; nt++) {
                int n = nbase + wn*64 + nt*8 + 2*tig;
                float v0 = ctx.acc[mt][nt][half*2 + 0];
                float v1 = ctx.acc[mt][nt][half*2 + 1];
                dst[n]   = tanhf(v0 + battn[n]);
                dst[n+1] = tanhf(v1 + battn[n+1]);
            }
        }
    }
}

// ---------------- gate epilogue ----------------
__global__ __launch_bounds__(256) void k_gate() {
    int j = blockIdx.x;
    int cnt = g_pcount[j*13];
    const int* list = g_plist + (j*13)*M_TOK;
    int t = threadIdx.x;
    for (int idx = blockIdx.y; idx < cnt; idx += gridDim.y) {
        int row = list[idx];
        const float* pre = g_pre + (size_t)row*GDIM + j*768;
        const float* nf  = g_rij + (size_t)row*KDIM + (1 + j)*768;
        float* cc = g_c + (size_t)row*GDIM + j*768;
        #pragma unroll
        for (int d = t; d < 768; d += 256) {
            float s = 1.f / (1.f + expf(-pre[d]));
            cc[d] = s * nf[d];
        }
    }
}

// ---------------- per-token Luong attention ----------------
__global__ __launch_bounds__(256) void k_attn(const float* __restrict__ seq) {
    int m = blockIdx.x;
    __shared__ float sseq[DIM];
    __shared__ float sc[NJ];
    __shared__ float sw[NJ];
    int t = threadIdx.x;
    for (int d = t; d < DIM; d += 256) sseq[d] = seq[(size_t)m*DIM + d];
    unsigned mask = g_amask[m];
    __syncthreads();

    int w = t >> 5, lane = t & 31;
    for (int j = w; j < NJ; j += 8) {
        float p = 0.f;
        if (mask & (1u << j)) {
            const float* cj = g_c + (size_t)m*GDIM + (size_t)j*DIM;
            for (int d = lane; d < DIM; d += 32) p += sseq[d]*cj[d];
            #pragma unroll
            for (int o = 16; o; o >>= 1) p += __shfl_xor_sync(0xffffffffu, p, o);
        }
        if (lane == 0) sc[j] = p;
    }
    __syncthreads();
    if (t == 0) {
        float mx = sc[0];
        #pragma unroll
        for (int j = 1; j < NJ; j++) mx = fmaxf(mx, sc[j]);
        float sum = 0.f;
        #pragma unroll
        for (int j = 0; j < NJ; j++) { float e = expf(sc[j]-mx); sw[j] = e; sum += e; }
        float inv = 1.f/sum;
        #pragma unroll
        for (int j = 0; j < NJ; j++) sw[j] *= inv;
    }
    __syncthreads();
    for (int d = t; d < DIM; d += 256) {
        float mix = 0.f;
        unsigned mm = mask;
        while (mm) {
            int j = __ffs(mm) - 1; mm &= mm - 1;
            mix += sw[j] * g_c[(size_t)m*GDIM + (size_t)j*DIM + d];
        }
        g_combined[(size_t)m*2*DIM + d]       = mix;
        g_combined[(size_t)m*2*DIM + DIM + d] = sseq[d];
        g_final[(size_t)m*2*DIM + d]          = sseq[d];
    }
}

// ---------------- classification head ----------------
__global__ void k_logits(const float* __restrict__ Wcls, const float* __restrict__ bcls,
                         float* __restrict__ out) {
    int m = blockIdx.x*8 + (threadIdx.x >> 5);
    int lane = threadIdx.x & 31;
    const float* f = g_final + (size_t)m*2*DIM;
    #pragma unroll
    for (int l = 0; l < NUM_LABELS; l++) {
        float p = 0.f;
        const float* wr = Wcls + (size_t)l*2*DIM;
        for (int d = lane; d < 2*DIM; d += 32) p += f[d]*wr[d];
        #pragma unroll
        for (int o = 16; o; o >>= 1) p += __shfl_xor_sync(0xffffffffu, p, o);
        if (lane == 0) out[m*NUM_LABELS + l] = p + bcls[l];
    }
}

// ---------------- launch ----------------
extern "C" void kernel_launch(void* const* d_in, const int* in_sizes, int n_in,
                              void* d_out, int out_size) {
    const float* seq   = (const float*)d_in[0];
    const int*   ids   = (const int*)  d_in[1];
    const int*   nb    = (const int*)  d_in[2];
    const float* Wmlp  = (const float*)d_in[3];
    const float* bmlp  = (const float*)d_in[4];
    const float* Wattn = (const float*)d_in[5];
    const float* battn = (const float*)d_in[6];
    const float* Wcls  = (const float*)d_in[7];
    const float* bcls  = (const float*)d_in[8];
    float* out = (float*)d_out;

    cudaFuncSetAttribute(k_mma_gemm<false>, cudaFuncAttributeMaxDynamicSharedMemorySize, SMEM_BYTES);
    cudaFuncSetAttribute(k_mma_gemm<true>,  cudaFuncAttributeMaxDynamicSharedMemorySize, SMEM_BYTES);
    cudaFuncSetAttribute(k_attnout_mma,     cudaFuncAttributeMaxDynamicSharedMemorySize, SMEM_BYTES);

    k_init<<<(V+255)/256, 256>>>();
    k_copy_seq<<<M_TOK, 192>>>(seq);
    for (int b = 0; b < NBATCH; b++) {
        k_scatter<<<1, SLEN>>>(ids + b*SLEN);
        k_fill<<<SLEN, 192>>>(ids + b*SLEN, seq + (size_t)b*SLEN*DIM);
        k_emb<<<SLEN*NJ, 192>>>(nb + (size_t)b*SLEN*NJ*NBK, b*SLEN);
        if (b + 1 < NBATCH) k_reset<<<1, SLEN>>>(ids + b*SLEN);
    }
    k_pairs<<<(M_TOK+255)/256, 256>>>();
    dim3 ga(8, 6, NJ);              // pass A: chunk 0 (seq), store + bias
    k_mma_gemm<false><<<ga, 256, SMEM_BYTES>>>(Wmlp, bmlp);
    dim3 gb(8, 6, NJ*NJ);           // pass B: chunks 1..12, atomic accumulate
    k_mma_gemm<true><<<gb, 256, SMEM_BYTES>>>(Wmlp, bmlp);
    dim3 gg(NJ, 16);
    k_gate<<<gg, 256>>>();
    k_attn<<<M_TOK, 256>>>(seq);
    dim3 go(M_TOK/128, 6);
    k_attnout_mma<<<go, 256, SMEM_BYTES>>>(Wattn, battn);
    k_logits<<<M_TOK/8, 256>>>(Wcls, bcls, out);
}

// round 6
// speedup vs baseline: 7.3023x; 1.2456x over previous
#include <cuda_runtime.h>
#include <cstdint>
#include <math.h>

#define V 30522
#define NBATCH 2
#define SLEN 512
#define DIM 768
#define NJ 12
#define NBK 4
#define NUM_LABELS 7
#define M_TOK (NBATCH*SLEN)   /* 1024 */
#define KDIM (13*DIM)         /* 9984 */
#define GDIM (NJ*DIM)         /* 9216 */
#define NPAIR (NJ*13)         /* 156 */

#define ROWP 36
#define STAGE_A_F ((128+128)*ROWP)        /* 128-tile stage floats */
#define SMEM_A_BYTES (2*STAGE_A_F*4)      /* 73728 */
#define STAGE_B_F ((64+128)*ROWP)         /* 64-tile stage floats */
#define SMEM_B_BYTES (2*STAGE_B_F*4)      /* 55296 */

// ---------------- scratch ----------------
__device__ int   g_lp0[V];
__device__ int   g_lp1[V];
__device__ float g_nflat[(size_t)M_TOK*GDIM];     // neighbor sums per (m, j)
__device__ float g_pre[(size_t)M_TOK*GDIM];       // pre-sigmoid gate
__device__ float g_combined[(size_t)M_TOK*2*DIM]; // [mix | seq]
__device__ float g_final[(size_t)M_TOK*2*DIM];    // [seq | attn_out]
__device__ unsigned int g_amask[M_TOK];
__device__ int   g_pcount[NPAIR];
__device__ int   g_plist[NPAIR*M_TOK];

// ---------------- helpers ----------------
__device__ __forceinline__ uint32_t smem_u32(const void* p) {
    uint32_t a; asm("{ .reg .u64 t; cvta.to.shared.u64 t, %1; cvt.u32.u64 %0, t; }" : "=r"(a) : "l"(p));
    return a;
}
__device__ __forceinline__ void cp16(uint32_t saddr, const void* g) {
    asm volatile("cp.async.ca.shared.global [%0], [%1], 16;" :: "r"(saddr), "l"(g));
}
#define CP_COMMIT() asm volatile("cp.async.commit_group;" ::: "memory")
#define CP_WAIT1()  asm volatile("cp.async.wait_group 1;" ::: "memory")
#define CP_WAIT0()  asm volatile("cp.async.wait_group 0;" ::: "memory")

__device__ __forceinline__ void mma_tf32(float* c, const uint32_t* a, const uint32_t* b) {
    asm volatile("mma.sync.aligned.m16n8k8.row.col.f32.tf32.tf32.f32 "
                 "{%0,%1,%2,%3}, {%4,%5,%6,%7}, {%8,%9}, {%0,%1,%2,%3};"
                 : "+f"(c[0]), "+f"(c[1]), "+f"(c[2]), "+f"(c[3])
                 : "r"(a[0]), "r"(a[1]), "r"(a[2]), "r"(a[3]), "r"(b[0]), "r"(b[1]));
}

// ---------------- small kernels ----------------
__global__ void k_init() {
    int i = blockIdx.x*blockDim.x + threadIdx.x;
    if (i < V) { g_lp0[i] = -1; g_lp1[i] = -1; }
    if (i < NPAIR) g_pcount[i] = 0;
    if (i < M_TOK) g_amask[i] = 0;
}

// FIX (R5 bug): select the device global INSIDE device code; passing g_lp0/g_lp1
// as a host-side kernel argument passed the host shadow address.
__global__ void k_scatter(const int* __restrict__ ids, int which) {
    int* lp = which ? g_lp1 : g_lp0;
    atomicMax(&lp[ids[threadIdx.x]], (int)threadIdx.x);
}

// One gather for all (b, s, j): resolve dict row = last occurrence in batches <= b.
__global__ void k_emb_all(const int* __restrict__ nb, const float* __restrict__ seq) {
    int blk = blockIdx.x;             // (b*512+s)*12 + j
    int j = blk % NJ;
    int m = blk / NJ;
    int b = m >> 9;
    const int* nbp = nb + (size_t)blk * NBK;
    int src[4];
    #pragma unroll
    for (int i = 0; i < 4; i++) {
        int id = nbp[i];
        int s0 = g_lp0[id];
        if (b) { int s1 = g_lp1[id]; src[i] = (s1 >= 0) ? (SLEN + s1) : s0; }
        else src[i] = s0;
    }
    if (src[0] < 0 && src[1] < 0 && src[2] < 0 && src[3] < 0) return;
    int t = threadIdx.x;              // 192 threads * float4 = 768
    float4 acc = make_float4(0.f,0.f,0.f,0.f);
    #pragma unroll
    for (int i = 0; i < 4; i++) {
        if (src[i] >= 0) {
            float4 v = ((const float4*)(seq + (size_t)src[i]*DIM))[t];
            acc.x += v.x; acc.y += v.y; acc.z += v.z; acc.w += v.w;
        }
    }
    ((float4*)(g_nflat + (size_t)m*GDIM + (size_t)j*DIM))[t] = acc;
    if (t == 0) atomicOr(&g_amask[m], 1u << j);
}

__global__ void k_pairs() {
    int m = blockIdx.x*256 + threadIdx.x;
    if (m >= M_TOK) return;
    unsigned mask = g_amask[m];
    if (!mask) return;
    unsigned mm = mask;
    while (mm) {
        int j = __ffs(mm) - 1; mm &= mm - 1;
        int base = j*13;
        int idx = atomicAdd(&g_pcount[base], 1);
        g_plist[base*M_TOK + idx] = m;
        unsigned m2 = mask;
        while (m2) {
            int c = __ffs(m2) - 1; m2 &= m2 - 1;
            int p = base + 1 + c;
            int idx2 = atomicAdd(&g_pcount[p], 1);
            g_plist[p*M_TOK + idx2] = m;
        }
    }
}

// ============ 128x128 mma stage (warps 4m x 2n, frags 2m x 8n) ============
__device__ __forceinline__ void mma_stage128(const uint32_t* sbase, int wm, int wn,
                                             int gid, int tig, float acc[2][8][4]) {
    const uint32_t* As = sbase;
    const uint32_t* Bs = sbase + 128*ROWP;
    #pragma unroll
    for (int ks = 0; ks < 4; ks++) {
        uint32_t a[2][4], b[8][2];
        #pragma unroll
        for (int mt = 0; mt < 2; mt++) {
            int r0 = wm*32 + mt*16 + gid;
            a[mt][0] = As[r0*ROWP + ks*8 + tig];
            a[mt][1] = As[(r0+8)*ROWP + ks*8 + tig];
            a[mt][2] = As[r0*ROWP + ks*8 + tig + 4];
            a[mt][3] = As[(r0+8)*ROWP + ks*8 + tig + 4];
        }
        #pragma unroll
        for (int nt = 0; nt < 8; nt++) {
            int n = wn*64 + nt*8 + gid;
            b[nt][0] = Bs[n*ROWP + ks*8 + tig];
            b[nt][1] = Bs[n*ROWP + ks*8 + tig + 4];
        }
        #pragma unroll
        for (int mt = 0; mt < 2; mt++)
            #pragma unroll
            for (int nt = 0; nt < 8; nt++)
                mma_tf32(acc[mt][nt], a[mt], b[nt]);
    }
}

// ============ 64x128 mma stage (warps 2m x 4n, frags 2m x 4n) ============
__device__ __forceinline__ void mma_stage64(const uint32_t* sbase, int wm, int wn,
                                            int gid, int tig, float acc[2][4][4]) {
    const uint32_t* As = sbase;
    const uint32_t* Bs = sbase + 64*ROWP;
    #pragma unroll
    for (int ks = 0; ks < 4; ks++) {
        uint32_t a[2][4], b[4][2];
        #pragma unroll
        for (int mt = 0; mt < 2; mt++) {
            int r0 = wm*32 + mt*16 + gid;
            a[mt][0] = As[r0*ROWP + ks*8 + tig];
            a[mt][1] = As[(r0+8)*ROWP + ks*8 + tig];
            a[mt][2] = As[r0*ROWP + ks*8 + tig + 4];
            a[mt][3] = As[(r0+8)*ROWP + ks*8 + tig + 4];
        }
        #pragma unroll
        for (int nt = 0; nt < 4; nt++) {
            int n = wn*32 + nt*8 + gid;
            b[nt][0] = Bs[n*ROWP + ks*8 + tig];
            b[nt][1] = Bs[n*ROWP + ks*8 + tig + 4];
        }
        #pragma unroll
        for (int mt = 0; mt < 2; mt++)
            #pragma unroll
            for (int nt = 0; nt < 4; nt++)
                mma_tf32(acc[mt][nt], a[mt], b[nt]);
    }
}

// ---------------- pass A: chunk 0 (seq), 128x128, store + bias ----------------
__global__ __launch_bounds__(256) void k_gemmA(const float* __restrict__ seq,
                                               const float* __restrict__ Wmlp,
                                               const float* __restrict__ bmlp) {
    int jout = blockIdx.z;
    int pid = jout*13;
    int cnt = g_pcount[pid];
    int m0 = blockIdx.x * 128;
    if (m0 >= cnt) return;
    int nbase = blockIdx.y * 128;

    extern __shared__ float smem[];
    __shared__ int rows_sh[128];
    uint32_t sb = smem_u32(smem);
    int tid = threadIdx.x;
    int wid = tid >> 5, lane = tid & 31;
    int gid = lane >> 2, tig = lane & 3;
    int wm = wid & 3, wn = wid >> 2;

    if (tid < 128) {
        int mi = m0 + tid;
        rows_sh[tid] = (mi < cnt) ? g_plist[pid*M_TOK + mi] : -1;
    }
    __syncthreads();

    const float* aptr[4]; const float* bptr[4];
    uint32_t sa[4], sbb[4];
    #pragma unroll
    for (int i = 0; i < 4; i++) {
        int idx = i*256 + tid;
        int row = idx >> 3, seg = idx & 7;
        int arow = rows_sh[row];
        aptr[i] = seq + (size_t)(arow < 0 ? 0 : arow)*DIM + seg*4;
        bptr[i] = Wmlp + (size_t)(jout*768 + nbase + row)*KDIM + seg*4;
        sa[i]  = sb + (row*ROWP + seg*4)*4;
        sbb[i] = sb + ((128*ROWP) + row*ROWP + seg*4)*4;
    }

    const int NS = 24;
    #pragma unroll
    for (int s = 0; s < 2; s++) {
        uint32_t so = s*STAGE_A_F*4;
        #pragma unroll
        for (int i = 0; i < 4; i++) {
            cp16(sa[i] + so,  aptr[i] + s*32);
            cp16(sbb[i] + so, bptr[i] + s*32);
        }
        CP_COMMIT();
    }

    float acc[2][8][4];
    #pragma unroll
    for (int mt = 0; mt < 2; mt++)
        #pragma unroll
        for (int nt = 0; nt < 8; nt++)
            #pragma unroll
            for (int q = 0; q < 4; q++) acc[mt][nt][q] = 0.f;

    for (int s = 0; s < NS; s++) {
        CP_WAIT1();
        __syncthreads();
        mma_stage128((const uint32_t*)smem + (s & 1)*STAGE_A_F, wm, wn, gid, tig, acc);
        __syncthreads();
        if (s + 2 < NS) {
            uint32_t so = ((s + 2) & 1)*STAGE_A_F*4;
            #pragma unroll
            for (int i = 0; i < 4; i++) {
                cp16(sa[i] + so,  aptr[i] + (s + 2)*32);
                cp16(sbb[i] + so, bptr[i] + (s + 2)*32);
            }
        }
        CP_COMMIT();
    }

    #pragma unroll
    for (int mt = 0; mt < 2; mt++) {
        #pragma unroll
        for (int half = 0; half < 2; half++) {
            int lr = wm*32 + mt*16 + gid + half*8;
            int row = rows_sh[lr];
            if (row < 0) continue;
            float* dst = g_pre + (size_t)row*GDIM + jout*768 + nbase;
            #pragma unroll
            for (int nt = 0; nt < 8; nt++) {
                int n = wn*64 + nt*8 + 2*tig;
                int gcol = jout*768 + nbase + n;
                dst[n]   = acc[mt][nt][half*2 + 0] + bmlp[gcol];
                dst[n+1] = acc[mt][nt][half*2 + 1] + bmlp[gcol+1];
            }
        }
    }
}

// ---------------- pass B: chunks 1..12, 64x128 tiles, atomic accumulate ----------------
__global__ __launch_bounds__(256) void k_gemmB(const float* __restrict__ Wmlp) {
    int jout = blockIdx.z / 12;
    int cc = blockIdx.z % 12;
    int chunk = cc + 1;
    int pid = jout*13 + chunk;
    int cnt = g_pcount[pid];
    if (cnt == 0) return;
    int nbase = blockIdx.y * 128;
    const int* list = g_plist + pid*M_TOK;

    extern __shared__ float smem[];
    __shared__ int rows_sh[64];
    uint32_t sb = smem_u32(smem);
    int tid = threadIdx.x;
    int wid = tid >> 5, lane = tid & 31;
    int gid = lane >> 2, tig = lane & 3;
    int wm = wid & 1, wn = wid >> 1;

    const float* bptr[4];
    uint32_t sbb[4];
    #pragma unroll
    for (int i = 0; i < 4; i++) {
        int idx = i*256 + tid;
        int row = idx >> 3, seg = idx & 7;
        bptr[i] = Wmlp + (size_t)(jout*768 + nbase + row)*KDIM + chunk*768 + seg*4;
        sbb[i] = sb + ((64*ROWP) + row*ROWP + seg*4)*4;
    }
    int arow_l[2]; int aseg[2]; uint32_t sa[2];
    #pragma unroll
    for (int i = 0; i < 2; i++) {
        int idx = i*256 + tid;
        arow_l[i] = idx >> 3; aseg[i] = idx & 7;
        sa[i] = sb + (arow_l[i]*ROWP + aseg[i]*4)*4;
    }

    const int NS = 24;
    for (int mt0 = blockIdx.x; mt0*64 < cnt; mt0 += gridDim.x) {
        int m0 = mt0*64;
        __syncthreads();
        if (tid < 64) {
            int mi = m0 + tid;
            rows_sh[tid] = (mi < cnt) ? list[mi] : -1;
        }
        __syncthreads();

        const float* aptr[2];
        #pragma unroll
        for (int i = 0; i < 2; i++) {
            int arow = rows_sh[arow_l[i]];
            aptr[i] = g_nflat + (size_t)(arow < 0 ? 0 : arow)*GDIM + cc*768 + aseg[i]*4;
        }

        #pragma unroll
        for (int s = 0; s < 2; s++) {
            uint32_t so = s*STAGE_B_F*4;
            #pragma unroll
            for (int i = 0; i < 2; i++) cp16(sa[i] + so, aptr[i] + s*32);
            #pragma unroll
            for (int i = 0; i < 4; i++) cp16(sbb[i] + so, bptr[i] + s*32);
            CP_COMMIT();
        }

        float acc[2][4][4];
        #pragma unroll
        for (int mt = 0; mt < 2; mt++)
            #pragma unroll
            for (int nt = 0; nt < 4; nt++)
                #pragma unroll
                for (int q = 0; q < 4; q++) acc[mt][nt][q] = 0.f;

        for (int s = 0; s < NS; s++) {
            CP_WAIT1();
            __syncthreads();
            mma_stage64((const uint32_t*)smem + (s & 1)*STAGE_B_F, wm, wn, gid, tig, acc);
            __syncthreads();
            if (s + 2 < NS) {
                uint32_t so = ((s + 2) & 1)*STAGE_B_F*4;
                #pragma unroll
                for (int i = 0; i < 2; i++) cp16(sa[i] + so, aptr[i] + (s + 2)*32);
                #pragma unroll
                for (int i = 0; i < 4; i++) cp16(sbb[i] + so, bptr[i] + (s + 2)*32);
            }
            CP_COMMIT();
        }
        CP_WAIT0();

        #pragma unroll
        for (int mt = 0; mt < 2; mt++) {
            #pragma unroll
            for (int half = 0; half < 2; half++) {
                int lr = wm*32 + mt*16 + gid + half*8;
                int row = rows_sh[lr];
                if (row < 0) continue;
                float* dst = g_pre + (size_t)row*GDIM + jout*768 + nbase;
                #pragma unroll
                for (int nt = 0; nt < 4; nt++) {
                    int n = wn*32 + nt*8 + 2*tig;
                    atomicAdd(&dst[n],   acc[mt][nt][half*2 + 0]);
                    atomicAdd(&dst[n+1], acc[mt][nt][half*2 + 1]);
                }
            }
        }
    }
}

// ---------------- fused gate + Luong attention + combined assembly ----------------
__global__ __launch_bounds__(256) void k_attn2(const float* __restrict__ seq) {
    extern __shared__ float sm[];
    float* sseq = sm;                 // 768
    float* cbuf = sm + DIM;           // 12*768
    __shared__ float sc[NJ], swt[NJ], red[8];
    int m = blockIdx.x, t = threadIdx.x;
    unsigned mask = g_amask[m];
    for (int d = t; d < DIM; d += 256) sseq[d] = seq[(size_t)m*DIM + d];
    if (t < NJ) sc[t] = 0.f;
    __syncthreads();

    unsigned mm = mask;
    while (mm) {
        int j = __ffs(mm) - 1; mm &= mm - 1;
        const float* pre = g_pre + (size_t)m*GDIM + j*768;
        const float* nf  = g_nflat + (size_t)m*GDIM + j*768;
        float part = 0.f;
        for (int d = t; d < DIM; d += 256) {
            float cv = (1.f / (1.f + expf(-pre[d]))) * nf[d];
            cbuf[j*768 + d] = cv;
            part += cv * sseq[d];
        }
        #pragma unroll
        for (int o = 16; o; o >>= 1) part += __shfl_xor_sync(0xffffffffu, part, o);
        if ((t & 31) == 0) red[t >> 5] = part;
        __syncthreads();
        if (t < 8) {
            float v = red[t];
            #pragma unroll
            for (int o = 4; o; o >>= 1) v += __shfl_xor_sync(0xffu, v, o);
            if (t == 0) sc[j] = v;
        }
        __syncthreads();
    }
    if (t == 0) {
        float mx = sc[0];
        #pragma unroll
        for (int j = 1; j < NJ; j++) mx = fmaxf(mx, sc[j]);
        float sum = 0.f;
        #pragma unroll
        for (int j = 0; j < NJ; j++) { float e = expf(sc[j]-mx); swt[j] = e; sum += e; }
        float inv = 1.f/sum;
        #pragma unroll
        for (int j = 0; j < NJ; j++) swt[j] *= inv;
    }
    __syncthreads();
    for (int d = t; d < DIM; d += 256) {
        float mix = 0.f;
        unsigned m2 = mask;
        while (m2) {
            int j = __ffs(m2) - 1; m2 &= m2 - 1;
            mix += swt[j] * cbuf[j*768 + d];
        }
        g_combined[(size_t)m*2*DIM + d]       = mix;
        g_combined[(size_t)m*2*DIM + DIM + d] = sseq[d];
        g_final[(size_t)m*2*DIM + d]          = sseq[d];
    }
}

// ---------------- attn_out GEMM: tanh(combined @ Wattn^T + b), 128x128 ----------------
__global__ __launch_bounds__(256) void k_attnout_mma(const float* __restrict__ Wattn,
                                                     const float* __restrict__ battn) {
    const int KD = 2*DIM;
    int m0 = blockIdx.x * 128;
    int nbase = blockIdx.y * 128;

    extern __shared__ float smem[];
    uint32_t sb = smem_u32(smem);
    int tid = threadIdx.x;
    int wid = tid >> 5, lane = tid & 31;
    int gid = lane >> 2, tig = lane & 3;
    int wm = wid & 3, wn = wid >> 2;

    const float* aptr[4]; const float* bptr[4];
    uint32_t sa[4], sbb[4];
    #pragma unroll
    for (int i = 0; i < 4; i++) {
        int idx = i*256 + tid;
        int row = idx >> 3, seg = idx & 7;
        aptr[i] = g_combined + (size_t)(m0 + row)*KD + seg*4;
        bptr[i] = Wattn + (size_t)(nbase + row)*KD + seg*4;
        sa[i]  = sb + (row*ROWP + seg*4)*4;
        sbb[i] = sb + ((128*ROWP) + row*ROWP + seg*4)*4;
    }

    const int NS = 48;
    #pragma unroll
    for (int s = 0; s < 2; s++) {
        uint32_t so = s*STAGE_A_F*4;
        #pragma unroll
        for (int i = 0; i < 4; i++) {
            cp16(sa[i] + so,  aptr[i] + s*32);
            cp16(sbb[i] + so, bptr[i] + s*32);
        }
        CP_COMMIT();
    }

    float acc[2][8][4];
    #pragma unroll
    for (int mt = 0; mt < 2; mt++)
        #pragma unroll
        for (int nt = 0; nt < 8; nt++)
            #pragma unroll
            for (int q = 0; q < 4; q++) acc[mt][nt][q] = 0.f;

    for (int s = 0; s < NS; s++) {
        CP_WAIT1();
        __syncthreads();
        mma_stage128((const uint32_t*)smem + (s & 1)*STAGE_A_F, wm, wn, gid, tig, acc);
        __syncthreads();
        if (s + 2 < NS) {
            uint32_t so = ((s + 2) & 1)*STAGE_A_F*4;
            #pragma unroll
            for (int i = 0; i < 4; i++) {
                cp16(sa[i] + so,  aptr[i] + (s + 2)*32);
                cp16(sbb[i] + so, bptr[i] + (s + 2)*32);
            }
        }
        CP_COMMIT();
    }

    #pragma unroll
    for (int mt = 0; mt < 2; mt++) {
        #pragma unroll
        for (int half = 0; half < 2; half++) {
            int m = m0 + wm*32 + mt*16 + gid + half*8;
            float* dst = g_final + (size_t)m*KD + DIM;
            #pragma unroll
            for (int nt = 0; nt < 8; nt++) {
                int n = nbase + wn*64 + nt*8 + 2*tig;
                dst[n]   = tanhf(acc[mt][nt][half*2 + 0] + battn[n]);
                dst[n+1] = tanhf(acc[mt][nt][half*2 + 1] + battn[n+1]);
            }
        }
    }
}

// ---------------- classification head ----------------
__global__ void k_logits(const float* __restrict__ Wcls, const float* __restrict__ bcls,
                         float* __restrict__ out) {
    int m = blockIdx.x*8 + (threadIdx.x >> 5);
    int lane = threadIdx.x & 31;
    const float* f = g_final + (size_t)m*2*DIM;
    #pragma unroll
    for (int l = 0; l < NUM_LABELS; l++) {
        float p = 0.f;
        const float* wr = Wcls + (size_t)l*2*DIM;
        for (int d = lane; d < 2*DIM; d += 32) p += f[d]*wr[d];
        #pragma unroll
        for (int o = 16; o; o >>= 1) p += __shfl_xor_sync(0xffffffffu, p, o);
        if (lane == 0) out[m*NUM_LABELS + l] = p + bcls[l];
    }
}

// ---------------- launch ----------------
extern "C" void kernel_launch(void* const* d_in, const int* in_sizes, int n_in,
                              void* d_out, int out_size) {
    const float* seq   = (const float*)d_in[0];
    const int*   ids   = (const int*)  d_in[1];
    const int*   nb    = (const int*)  d_in[2];
    const float* Wmlp  = (const float*)d_in[3];
    const float* bmlp  = (const float*)d_in[4];
    const float* Wattn = (const float*)d_in[5];
    const float* battn = (const float*)d_in[6];
    const float* Wcls  = (const float*)d_in[7];
    const float* bcls  = (const float*)d_in[8];
    float* out = (float*)d_out;

    cudaFuncSetAttribute(k_gemmA,       cudaFuncAttributeMaxDynamicSharedMemorySize, SMEM_A_BYTES);
    cudaFuncSetAttribute(k_gemmB,       cudaFuncAttributeMaxDynamicSharedMemorySize, SMEM_B_BYTES);
    cudaFuncSetAttribute(k_attnout_mma, cudaFuncAttributeMaxDynamicSharedMemorySize, SMEM_A_BYTES);

    k_init<<<(V+255)/256, 256>>>();
    k_scatter<<<1, SLEN>>>(ids, 0);
    k_scatter<<<1, SLEN>>>(ids + SLEN, 1);
    k_emb_all<<<M_TOK*NJ, 192>>>(nb, seq);
    k_pairs<<<(M_TOK+255)/256, 256>>>();
    dim3 ga(8, 6, NJ);
    k_gemmA<<<ga, 256, SMEM_A_BYTES>>>(seq, Wmlp, bmlp);
    dim3 gb(4, 6, NJ*NJ);
    k_gemmB<<<gb, 256, SMEM_B_BYTES>>>(Wmlp);
    int attn_smem = (DIM + NJ*DIM)*4;     // ~40KB
    k_attn2<<<M_TOK, 256, attn_smem>>>(seq);
    dim3 go(M_TOK/128, 6);
    k_attnout_mma<<<go, 256, SMEM_A_BYTES>>>(Wattn, battn);
    k_logits<<<M_TOK/8, 256>>>(Wcls, bcls, out);
}

// round 7
// speedup vs baseline: 9.0746x; 1.2427x over previous
#include <cuda_runtime.h>
#include <cstdint>
#include <math.h>

#define V 30522
#define NBATCH 2
#define SLEN 512
#define DIM 768
#define NJ 12
#define NBK 4
#define NUM_LABELS 7
#define M_TOK (NBATCH*SLEN)   /* 1024 */
#define KDIM (13*DIM)         /* 9984 */
#define GDIM (NJ*DIM)         /* 9216 */
#define NPAIR (NJ*13)         /* 156 */

#define ROWP 36
#define STAGE_F ((64+128)*ROWP)           /* 6912 floats per stage */
#define SMEM_U_BYTES (3*STAGE_F*4)        /* 82944: 3-stage pipeline */

// ---------------- scratch ----------------
__device__ int   g_lp0[V];
__device__ int   g_lp1[V];
__device__ float g_nflat[(size_t)M_TOK*GDIM];     // neighbor sums per (m, j)
__device__ float g_pre[(size_t)M_TOK*GDIM];       // gate accumulator (bias-seeded)
__device__ float g_combined[(size_t)M_TOK*2*DIM]; // [mix | seq]
__device__ float g_final[(size_t)M_TOK*2*DIM];    // [seq | attn_out]
__device__ unsigned int g_amask[M_TOK];
__device__ int   g_pcount[NPAIR];
__device__ int   g_plist[NPAIR*M_TOK];

// ---------------- helpers ----------------
__device__ __forceinline__ uint32_t smem_u32(const void* p) {
    uint32_t a; asm("{ .reg .u64 t; cvta.to.shared.u64 t, %1; cvt.u32.u64 %0, t; }" : "=r"(a) : "l"(p));
    return a;
}
__device__ __forceinline__ void cp16(uint32_t saddr, const void* g) {
    asm volatile("cp.async.ca.shared.global [%0], [%1], 16;" :: "r"(saddr), "l"(g));
}
#define CP_COMMIT() asm volatile("cp.async.commit_group;" ::: "memory")
#define CP_WAIT2()  asm volatile("cp.async.wait_group 2;" ::: "memory")

__device__ __forceinline__ void mma_tf32(float* c, const uint32_t* a, const uint32_t* b) {
    asm volatile("mma.sync.aligned.m16n8k8.row.col.f32.tf32.tf32.f32 "
                 "{%0,%1,%2,%3}, {%4,%5,%6,%7}, {%8,%9}, {%0,%1,%2,%3};"
                 : "+f"(c[0]), "+f"(c[1]), "+f"(c[2]), "+f"(c[3])
                 : "r"(a[0]), "r"(a[1]), "r"(a[2]), "r"(a[3]), "r"(b[0]), "r"(b[1]));
}

// ---------------- small kernels ----------------
__global__ void k_init() {
    int i = blockIdx.x*blockDim.x + threadIdx.x;
    if (i < V) { g_lp0[i] = -1; g_lp1[i] = -1; }
    if (i < NPAIR) g_pcount[i] = 0;
    if (i < M_TOK) g_amask[i] = 0;
}
__global__ void k_scatter(const int* __restrict__ ids, int which) {
    int* lp = which ? g_lp1 : g_lp0;
    atomicMax(&lp[ids[threadIdx.x]], (int)threadIdx.x);
}

// Gather neighbor sums + seed g_pre with bias for every active (m, j).
__global__ void k_emb_all(const int* __restrict__ nb, const float* __restrict__ seq,
                          const float* __restrict__ bmlp) {
    int blk = blockIdx.x;             // (b*512+s)*12 + j
    int j = blk % NJ;
    int m = blk / NJ;
    int b = m >> 9;
    const int* nbp = nb + (size_t)blk * NBK;
    int src[4];
    #pragma unroll
    for (int i = 0; i < 4; i++) {
        int id = nbp[i];
        int s0 = g_lp0[id];
        if (b) { int s1 = g_lp1[id]; src[i] = (s1 >= 0) ? (SLEN + s1) : s0; }
        else src[i] = s0;
    }
    if (src[0] < 0 && src[1] < 0 && src[2] < 0 && src[3] < 0) return;
    int t = threadIdx.x;              // 192 threads * float4 = 768
    float4 acc = make_float4(0.f,0.f,0.f,0.f);
    #pragma unroll
    for (int i = 0; i < 4; i++) {
        if (src[i] >= 0) {
            float4 v = ((const float4*)(seq + (size_t)src[i]*DIM))[t];
            acc.x += v.x; acc.y += v.y; acc.z += v.z; acc.w += v.w;
        }
    }
    ((float4*)(g_nflat + (size_t)m*GDIM + (size_t)j*DIM))[t] = acc;
    // seed the gate accumulator with the bias (plain store; GEMM adds on top)
    float4 bv = ((const float4*)(bmlp + (size_t)j*DIM))[t];
    ((float4*)(g_pre + (size_t)m*GDIM + (size_t)j*DIM))[t] = bv;
    if (t == 0) atomicOr(&g_amask[m], 1u << j);
}

__global__ void k_pairs() {
    int m = blockIdx.x*256 + threadIdx.x;
    if (m >= M_TOK) return;
    unsigned mask = g_amask[m];
    if (!mask) return;
    unsigned mm = mask;
    while (mm) {
        int j = __ffs(mm) - 1; mm &= mm - 1;
        int base = j*13;
        int idx = atomicAdd(&g_pcount[base], 1);
        g_plist[base*M_TOK + idx] = m;
        unsigned m2 = mask;
        while (m2) {
            int c = __ffs(m2) - 1; m2 &= m2 - 1;
            int p = base + 1 + c;
            int idx2 = atomicAdd(&g_pcount[p], 1);
            g_plist[p*M_TOK + idx2] = m;
        }
    }
}

// ============ 64x128 mma stage (warps 2m x 4n, frags 2m x 4n) ============
__device__ __forceinline__ void mma_stage64(const uint32_t* sbase, int wm, int wn,
                                            int gid, int tig, float acc[2][4][4]) {
    const uint32_t* As = sbase;
    const uint32_t* Bs = sbase + 64*ROWP;
    #pragma unroll
    for (int ks = 0; ks < 4; ks++) {
        uint32_t a[2][4], b[4][2];
        #pragma unroll
        for (int mt = 0; mt < 2; mt++) {
            int r0 = wm*32 + mt*16 + gid;
            a[mt][0] = As[r0*ROWP + ks*8 + tig];
            a[mt][1] = As[(r0+8)*ROWP + ks*8 + tig];
            a[mt][2] = As[r0*ROWP + ks*8 + tig + 4];
            a[mt][3] = As[(r0+8)*ROWP + ks*8 + tig + 4];
        }
        #pragma unroll
        for (int nt = 0; nt < 4; nt++) {
            int n = wn*32 + nt*8 + gid;
            b[nt][0] = Bs[n*ROWP + ks*8 + tig];
            b[nt][1] = Bs[n*ROWP + ks*8 + tig + 4];
        }
        #pragma unroll
        for (int mt = 0; mt < 2; mt++)
            #pragma unroll
            for (int nt = 0; nt < 4; nt++)
                mma_tf32(acc[mt][nt], a[mt], b[nt]);
    }
}

// ---------------- unified sparse GEMM: all 156 (jout, chunk) pairs ----------------
__global__ __launch_bounds__(256) void k_gemmU(const float* __restrict__ seq,
                                               const float* __restrict__ Wmlp) {
    int pid = blockIdx.z;             // jout*13 + chunk
    int jout = pid / 13, chunk = pid % 13;
    int cnt = g_pcount[pid];
    if (cnt == 0) return;
    int nbase = blockIdx.y * 128;
    const int* list = g_plist + pid*M_TOK;

    const float* abase = chunk ? (g_nflat + (size_t)(chunk-1)*768) : seq;
    size_t astride = chunk ? (size_t)GDIM : (size_t)DIM;

    extern __shared__ float smem[];
    __shared__ int rows_sh[64];
    uint32_t sb = smem_u32(smem);
    int tid = threadIdx.x;
    int wid = tid >> 5, lane = tid & 31;
    int gid = lane >> 2, tig = lane & 3;
    int wm = wid & 1, wn = wid >> 1;

    // B assignments (fixed): 4 per thread
    const float* bptr[4];
    uint32_t sbb[4];
    #pragma unroll
    for (int i = 0; i < 4; i++) {
        int idx = i*256 + tid;
        int row = idx >> 3, seg = idx & 7;
        bptr[i] = Wmlp + (size_t)(jout*768 + nbase + row)*KDIM + chunk*768 + seg*4;
        sbb[i] = sb + ((64*ROWP) + row*ROWP + seg*4)*4;
    }
    // A assignments: 2 per thread
    int arow_l[2]; int aseg[2]; uint32_t sa[2];
    #pragma unroll
    for (int i = 0; i < 2; i++) {
        int idx = i*256 + tid;
        arow_l[i] = idx >> 3; aseg[i] = idx & 7;
        sa[i] = sb + (arow_l[i]*ROWP + aseg[i]*4)*4;
    }

    const int NS = 24;
    for (int mt0 = blockIdx.x; mt0*64 < cnt; mt0 += gridDim.x) {
        int m0 = mt0*64;
        __syncthreads();              // protect rows_sh across m-tile iterations
        if (tid < 64) {
            int mi = m0 + tid;
            rows_sh[tid] = (mi < cnt) ? list[mi] : -1;
        }
        __syncthreads();

        const float* aptr[2];
        #pragma unroll
        for (int i = 0; i < 2; i++) {
            int arow = rows_sh[arow_l[i]];
            aptr[i] = abase + (size_t)(arow < 0 ? 0 : arow)*astride + aseg[i]*4;
        }

        // prologue: 3 stages in flight
        #pragma unroll
        for (int s = 0; s < 3; s++) {
            uint32_t so = s*STAGE_F*4;
            #pragma unroll
            for (int i = 0; i < 2; i++) cp16(sa[i] + so, aptr[i] + s*32);
            #pragma unroll
            for (int i = 0; i < 4; i++) cp16(sbb[i] + so, bptr[i] + s*32);
            CP_COMMIT();
        }

        float acc[2][4][4];
        #pragma unroll
        for (int mt = 0; mt < 2; mt++)
            #pragma unroll
            for (int nt = 0; nt < 4; nt++)
                #pragma unroll
                for (int q = 0; q < 4; q++) acc[mt][nt][q] = 0.f;

        for (int s = 0; s < NS; s++) {
            CP_WAIT2();
            __syncthreads();
            int slot = s % 3;
            mma_stage64((const uint32_t*)smem + slot*STAGE_F, wm, wn, gid, tig, acc);
            __syncthreads();
            if (s + 3 < NS) {
                uint32_t so = slot*STAGE_F*4;
                #pragma unroll
                for (int i = 0; i < 2; i++) cp16(sa[i] + so, aptr[i] + (s + 3)*32);
                #pragma unroll
                for (int i = 0; i < 4; i++) cp16(sbb[i] + so, bptr[i] + (s + 3)*32);
            }
            CP_COMMIT();
        }

        #pragma unroll
        for (int mt = 0; mt < 2; mt++) {
            #pragma unroll
            for (int half = 0; half < 2; half++) {
                int lr = wm*32 + mt*16 + gid + half*8;
                int row = rows_sh[lr];
                if (row < 0) continue;
                float* dst = g_pre + (size_t)row*GDIM + jout*768 + nbase;
                #pragma unroll
                for (int nt = 0; nt < 4; nt++) {
                    int n = wn*32 + nt*8 + 2*tig;
                    atomicAdd(&dst[n],   acc[mt][nt][half*2 + 0]);
                    atomicAdd(&dst[n+1], acc[mt][nt][half*2 + 1]);
                }
            }
        }
    }
}

// ---------------- fused gate + Luong attention + combined assembly ----------------
__global__ __launch_bounds__(256) void k_attn2(const float* __restrict__ seq) {
    extern __shared__ float sm[];
    float* sseq = sm;                 // 768
    float* cbuf = sm + DIM;           // 12*768
    __shared__ float sc[NJ], swt[NJ], red[8];
    int m = blockIdx.x, t = threadIdx.x;
    unsigned mask = g_amask[m];
    for (int d = t; d < DIM; d += 256) sseq[d] = seq[(size_t)m*DIM + d];
    if (t < NJ) sc[t] = 0.f;
    __syncthreads();

    unsigned mm = mask;
    while (mm) {
        int j = __ffs(mm) - 1; mm &= mm - 1;
        const float* pre = g_pre + (size_t)m*GDIM + j*768;
        const float* nf  = g_nflat + (size_t)m*GDIM + j*768;
        float part = 0.f;
        for (int d = t; d < DIM; d += 256) {
            float cv = (1.f / (1.f + expf(-pre[d]))) * nf[d];
            cbuf[j*768 + d] = cv;
            part += cv * sseq[d];
        }
        #pragma unroll
        for (int o = 16; o; o >>= 1) part += __shfl_xor_sync(0xffffffffu, part, o);
        if ((t & 31) == 0) red[t >> 5] = part;
        __syncthreads();
        if (t < 8) {
            float v = red[t];
            #pragma unroll
            for (int o = 4; o; o >>= 1) v += __shfl_xor_sync(0xffu, v, o);
            if (t == 0) sc[j] = v;
        }
        __syncthreads();
    }
    if (t == 0) {
        float mx = sc[0];
        #pragma unroll
        for (int j = 1; j < NJ; j++) mx = fmaxf(mx, sc[j]);
        float sum = 0.f;
        #pragma unroll
        for (int j = 0; j < NJ; j++) { float e = expf(sc[j]-mx); swt[j] = e; sum += e; }
        float inv = 1.f/sum;
        #pragma unroll
        for (int j = 0; j < NJ; j++) swt[j] *= inv;
    }
    __syncthreads();
    for (int d = t; d < DIM; d += 256) {
        float mix = 0.f;
        unsigned m2 = mask;
        while (m2) {
            int j = __ffs(m2) - 1; m2 &= m2 - 1;
            mix += swt[j] * cbuf[j*768 + d];
        }
        g_combined[(size_t)m*2*DIM + d]       = mix;
        g_combined[(size_t)m*2*DIM + DIM + d] = sseq[d];
        g_final[(size_t)m*2*DIM + d]          = sseq[d];
    }
}

// ---------------- attn_out GEMM: tanh(combined @ Wattn^T + b), 64x128, 3-stage ----------------
__global__ __launch_bounds__(256) void k_attnout_mma(const float* __restrict__ Wattn,
                                                     const float* __restrict__ battn) {
    const int KD = 2*DIM;             // 1536
    int m0 = blockIdx.x * 64;
    int nbase = blockIdx.y * 128;

    extern __shared__ float smem[];
    uint32_t sb = smem_u32(smem);
    int tid = threadIdx.x;
    int wid = tid >> 5, lane = tid & 31;
    int gid = lane >> 2, tig = lane & 3;
    int wm = wid & 1, wn = wid >> 1;

    const float* bptr[4];
    uint32_t sbb[4];
    #pragma unroll
    for (int i = 0; i < 4; i++) {
        int idx = i*256 + tid;
        int row = idx >> 3, seg = idx & 7;
        bptr[i] = Wattn + (size_t)(nbase + row)*KD + seg*4;
        sbb[i] = sb + ((64*ROWP) + row*ROWP + seg*4)*4;
    }
    const float* aptr[2];
    uint32_t sa[2];
    #pragma unroll
    for (int i = 0; i < 2; i++) {
        int idx = i*256 + tid;
        int row = idx >> 3, seg = idx & 7;
        aptr[i] = g_combined + (size_t)(m0 + row)*KD + seg*4;
        sa[i] = sb + (row*ROWP + seg*4)*4;
    }

    const int NS = 48;
    #pragma unroll
    for (int s = 0; s < 3; s++) {
        uint32_t so = s*STAGE_F*4;
        #pragma unroll
        for (int i = 0; i < 2; i++) cp16(sa[i] + so, aptr[i] + s*32);
        #pragma unroll
        for (int i = 0; i < 4; i++) cp16(sbb[i] + so, bptr[i] + s*32);
        CP_COMMIT();
    }

    float acc[2][4][4];
    #pragma unroll
    for (int mt = 0; mt < 2; mt++)
        #pragma unroll
        for (int nt = 0; nt < 4; nt++)
            #pragma unroll
            for (int q = 0; q < 4; q++) acc[mt][nt][q] = 0.f;

    for (int s = 0; s < NS; s++) {
        CP_WAIT2();
        __syncthreads();
        int slot = s % 3;
        mma_stage64((const uint32_t*)smem + slot*STAGE_F, wm, wn, gid, tig, acc);
        __syncthreads();
        if (s + 3 < NS) {
            uint32_t so = slot*STAGE_F*4;
            #pragma unroll
            for (int i = 0; i < 2; i++) cp16(sa[i] + so, aptr[i] + (s + 3)*32);
            #pragma unroll
            for (int i = 0; i < 4; i++) cp16(sbb[i] + so, bptr[i] + (s + 3)*32);
        }
        CP_COMMIT();
    }

    #pragma unroll
    for (int mt = 0; mt < 2; mt++) {
        #pragma unroll
        for (int half = 0; half < 2; half++) {
            int m = m0 + wm*32 + mt*16 + gid + half*8;
            float* dst = g_final + (size_t)m*KD + DIM;
            #pragma unroll
            for (int nt = 0; nt < 4; nt++) {
                int n = nbase + wn*32 + nt*8 + 2*tig;
                dst[n]   = tanhf(acc[mt][nt][half*2 + 0] + battn[n]);
                dst[n+1] = tanhf(acc[mt][nt][half*2 + 1] + battn[n+1]);
            }
        }
    }
}

// ---------------- classification head ----------------
__global__ void k_logits(const float* __restrict__ Wcls, const float* __restrict__ bcls,
                         float* __restrict__ out) {
    int m = blockIdx.x*8 + (threadIdx.x >> 5);
    int lane = threadIdx.x & 31;
    const float* f = g_final + (size_t)m*2*DIM;
    #pragma unroll
    for (int l = 0; l < NUM_LABELS; l++) {
        float p = 0.f;
        const float* wr = Wcls + (size_t)l*2*DIM;
        for (int d = lane; d < 2*DIM; d += 32) p += f[d]*wr[d];
        #pragma unroll
        for (int o = 16; o; o >>= 1) p += __shfl_xor_sync(0xffffffffu, p, o);
        if (lane == 0) out[m*NUM_LABELS + l] = p + bcls[l];
    }
}

// ---------------- launch ----------------
extern "C" void kernel_launch(void* const* d_in, const int* in_sizes, int n_in,
                              void* d_out, int out_size) {
    const float* seq   = (const float*)d_in[0];
    const int*   ids   = (const int*)  d_in[1];
    const int*   nb    = (const int*)  d_in[2];
    const float* Wmlp  = (const float*)d_in[3];
    const float* bmlp  = (const float*)d_in[4];
    const float* Wattn = (const float*)d_in[5];
    const float* battn = (const float*)d_in[6];
    const float* Wcls  = (const float*)d_in[7];
    const float* bcls  = (const float*)d_in[8];
    float* out = (float*)d_out;

    cudaFuncSetAttribute(k_gemmU,       cudaFuncAttributeMaxDynamicSharedMemorySize, SMEM_U_BYTES);
    cudaFuncSetAttribute(k_attnout_mma, cudaFuncAttributeMaxDynamicSharedMemorySize, SMEM_U_BYTES);

    k_init<<<(V+255)/256, 256>>>();
    k_scatter<<<1, SLEN>>>(ids, 0);
    k_scatter<<<1, SLEN>>>(ids + SLEN, 1);
    k_emb_all<<<M_TOK*NJ, 192>>>(nb, seq, bmlp);
    k_pairs<<<(M_TOK+255)/256, 256>>>();
    dim3 gu(3, 6, NPAIR);             // unified: all (jout, chunk) pairs, atomic accumulate
    k_gemmU<<<gu, 256, SMEM_U_BYTES>>>(seq, Wmlp);
    int attn_smem = (DIM + NJ*DIM)*4; // ~40KB
    k_attn2<<<M_TOK, 256, attn_smem>>>(seq);
    dim3 go(M_TOK/64, 6);             // 96 CTAs
    k_attnout_mma<<<go, 256, SMEM_U_BYTES>>>(Wattn, battn);
    k_logits<<<M_TOK/8, 256>>>(Wcls, bcls, out);
}